// round 15
// baseline (speedup 1.0000x reference)
#include <cuda_runtime.h>
#include <math.h>

#define FULLMASK 0xffffffffu

// ---------------- scratch (__device__ globals; no allocs allowed) ----------------
__device__ float g_q[16 * 1024 * 64];    // [b*H][s][dk]
__device__ float g_k[16 * 1024 * 64];
__device__ float g_v[16 * 1024 * 64];
__device__ float g_attn[16 * 1024 * 64]; // attention output, same row layout
__device__ float g_qn[8 * 2048 * 64];    // normalized+scaled q_mem  [h][q][dk]
__device__ float g_kn[8 * 8192 * 64];    // normalized key memories  [h][m][dk]
__device__ float g_sim[8 * 2048 * 8192]; // fp32 sims, all heads (512 MB)
__device__ float g_wsum[8 * 2048 * 64];  // memory-path weighted sums [h][q][dk]
__device__ float g_pre[2048 * 512];      // pre-Wo combined activations

// ---------------- generic 128x128 tile SGEMM body (R1-verbatim arithmetic) -------
template <bool BT, bool HEADS>
__device__ __forceinline__ void gemm128_body(
    const float* __restrict__ A, int lda,
    const float* __restrict__ B, int ldb,
    const float* __restrict__ bias,
    float* __restrict__ C, int N, int K)
{
    __shared__ float As[128 * 33];
    __shared__ float Bs[4224];   // NT: [128][33] ; NN: [32][132]
    const int tid = threadIdx.x;
    const int tx = tid & 15, ty = tid >> 4;
    const int n0 = blockIdx.x * 128, m0 = blockIdx.y * 128;

    float acc[8][8];
#pragma unroll
    for (int i = 0; i < 8; i++)
#pragma unroll
        for (int j = 0; j < 8; j++) acc[i][j] = 0.f;

    for (int kt = 0; kt < K; kt += 32) {
#pragma unroll
        for (int t = 0; t < 4; t++) {               // A tile: 128 rows x 32 cols
            int li = tid + 256 * t;
            int row = li >> 3, c4 = li & 7;
            float4 va = *(const float4*)(A + (size_t)(m0 + row) * lda + kt + c4 * 4);
            float* dst = &As[row * 33 + c4 * 4];
            dst[0] = va.x; dst[1] = va.y; dst[2] = va.z; dst[3] = va.w;
        }
        if (BT) {
#pragma unroll
            for (int t = 0; t < 4; t++) {           // B tile: 128 rows x 32 cols
                int li = tid + 256 * t;
                int row = li >> 3, c4 = li & 7;
                float4 vb = *(const float4*)(B + (size_t)(n0 + row) * ldb + kt + c4 * 4);
                float* dst = &Bs[row * 33 + c4 * 4];
                dst[0] = vb.x; dst[1] = vb.y; dst[2] = vb.z; dst[3] = vb.w;
            }
        } else {
#pragma unroll
            for (int t = 0; t < 4; t++) {           // B tile: 32 rows x 128 cols
                int li = tid + 256 * t;
                int row = li >> 5, c4 = li & 31;
                float4 vb = *(const float4*)(B + (size_t)(kt + row) * ldb + n0 + c4 * 4);
                float* dst = &Bs[row * 132 + c4 * 4];
                dst[0] = vb.x; dst[1] = vb.y; dst[2] = vb.z; dst[3] = vb.w;
            }
        }
        __syncthreads();
#pragma unroll 4
        for (int d = 0; d < 32; d++) {
            float a[8], b[8];
#pragma unroll
            for (int i = 0; i < 8; i++) a[i] = As[(ty + 16 * i) * 33 + d];
#pragma unroll
            for (int j = 0; j < 8; j++)
                b[j] = BT ? Bs[(tx + 16 * j) * 33 + d] : Bs[d * 132 + tx + 16 * j];
#pragma unroll
            for (int i = 0; i < 8; i++)
#pragma unroll
                for (int j = 0; j < 8; j++) acc[i][j] += a[i] * b[j];
        }
        __syncthreads();
    }

#pragma unroll
    for (int i = 0; i < 8; i++) {
        int m = m0 + ty + 16 * i;
#pragma unroll
        for (int j = 0; j < 8; j++) {
            int n = n0 + tx + 16 * j;
            float val = acc[i][j] + (bias ? bias[n] : 0.f);
            if (HEADS) {
                int bb = m >> 10, ss = m & 1023, hh = n >> 6, dd = n & 63;
                C[(size_t)(((bb << 3) + hh) << 16) + (ss << 6) + dd] = val;
            } else {
                C[(size_t)m * N + n] = val;
            }
        }
    }
}

// fused QKV: blockIdx.z selects projection; body identical -> identical arithmetic
__global__ __launch_bounds__(256) void gemmqkv_kernel(
    const float* __restrict__ x,
    const float* __restrict__ Wq, const float* __restrict__ bq,
    const float* __restrict__ Wk, const float* __restrict__ bk,
    const float* __restrict__ Wv, const float* __restrict__ bv)
{
    const int z = blockIdx.z;
    const float* W = (z == 0) ? Wq : (z == 1) ? Wk : Wv;
    const float* b = (z == 0) ? bq : (z == 1) ? bk : bv;
    float* C = (z == 0) ? g_q : (z == 1) ? g_k : g_v;
    gemm128_body<false, true>(x, 512, W, 512, b, C, 512, 512);
}

// ---------------- out projection: 64x64 tiles (chain-identical, 256 CTAs) --------
// Per-element accumulation order (kt += 32, d 0..31 ascending) matches gemm128
// exactly -> bit-identical to the 128x128 version.
__global__ __launch_bounds__(256) void gemmout64_kernel(
    const float* __restrict__ Wo, const float* __restrict__ bo, float* __restrict__ out)
{
    __shared__ float As[64 * 33];
    __shared__ float Bs[32 * 68];
    const int tid = threadIdx.x;
    const int tx = tid & 15, ty = tid >> 4;
    const int n0 = blockIdx.x * 64, m0 = blockIdx.y * 64;
    const float* A = g_pre;

    float acc[4][4];
#pragma unroll
    for (int i = 0; i < 4; i++)
#pragma unroll
        for (int j = 0; j < 4; j++) acc[i][j] = 0.f;

    for (int kt = 0; kt < 512; kt += 32) {
#pragma unroll
        for (int t = 0; t < 2; t++) {               // A tile: 64 rows x 32 cols
            int li = tid + 256 * t;                 // 0..511
            int row = li >> 3, c4 = li & 7;
            float4 va = *(const float4*)(A + (size_t)(m0 + row) * 512 + kt + c4 * 4);
            float* dst = &As[row * 33 + c4 * 4];
            dst[0] = va.x; dst[1] = va.y; dst[2] = va.z; dst[3] = va.w;
        }
#pragma unroll
        for (int t = 0; t < 2; t++) {               // B tile: 32 rows x 64 cols
            int li = tid + 256 * t;
            int row = li >> 4, c4 = li & 15;
            float4 vb = *(const float4*)(Wo + (size_t)(kt + row) * 512 + n0 + c4 * 4);
            float* dst = &Bs[row * 68 + c4 * 4];
            dst[0] = vb.x; dst[1] = vb.y; dst[2] = vb.z; dst[3] = vb.w;
        }
        __syncthreads();
#pragma unroll 4
        for (int d = 0; d < 32; d++) {
            float a[4], b[4];
#pragma unroll
            for (int i = 0; i < 4; i++) a[i] = As[(ty + 16 * i) * 33 + d];
#pragma unroll
            for (int j = 0; j < 4; j++) b[j] = Bs[d * 68 + tx + 16 * j];
#pragma unroll
            for (int i = 0; i < 4; i++)
#pragma unroll
                for (int j = 0; j < 4; j++) acc[i][j] += a[i] * b[j];
        }
        __syncthreads();
    }

#pragma unroll
    for (int i = 0; i < 4; i++) {
        int m = m0 + ty + 16 * i;
#pragma unroll
        for (int j = 0; j < 4; j++) {
            int n = n0 + tx + 16 * j;
            out[(size_t)m * 512 + n] = acc[i][j] + bo[n];
        }
    }
}

// ---------------- fast sims SGEMM (R10-verbatim: transposed smem + lds.128) ------
__global__ __launch_bounds__(256) void simsgemm_kernel()
{
    __shared__ float At[32 * 128];
    __shared__ float Bt[32 * 128];
    const int h = blockIdx.z;
    const int n0 = blockIdx.x * 128, m0 = blockIdx.y * 128;
    const int tid = threadIdx.x;
    const int tx = tid & 15, ty = tid >> 4;
    const float* A = g_qn + (size_t)h * 2048 * 64 + (size_t)m0 * 64;
    const float* B = g_kn + (size_t)h * 8192 * 64 + (size_t)n0 * 64;

    float acc[8][8];
#pragma unroll
    for (int i = 0; i < 8; i++)
#pragma unroll
        for (int j = 0; j < 8; j++) acc[i][j] = 0.f;

    for (int kc = 0; kc < 64; kc += 32) {
        if (kc) __syncthreads();
#pragma unroll
        for (int t = 0; t < 4; t++) {               // 1024 float4 per tile, transposed store
            int li = tid + 256 * t;                 // 0..1023
            int c4 = li >> 7;                       // 0..7 (float4 column within chunk)
            int row = li & 127;                     // tile row
            float4 va = *(const float4*)(A + (size_t)row * 64 + kc + c4 * 4);
            At[(c4 * 4 + 0) * 128 + row] = va.x;
            At[(c4 * 4 + 1) * 128 + row] = va.y;
            At[(c4 * 4 + 2) * 128 + row] = va.z;
            At[(c4 * 4 + 3) * 128 + row] = va.w;
            float4 vb = *(const float4*)(B + (size_t)row * 64 + kc + c4 * 4);
            Bt[(c4 * 4 + 0) * 128 + row] = vb.x;
            Bt[(c4 * 4 + 1) * 128 + row] = vb.y;
            Bt[(c4 * 4 + 2) * 128 + row] = vb.z;
            Bt[(c4 * 4 + 3) * 128 + row] = vb.w;
        }
        __syncthreads();

#pragma unroll 8
        for (int d = 0; d < 32; d++) {
            float4 a0 = *(const float4*)&At[d * 128 + ty * 8];
            float4 a1 = *(const float4*)&At[d * 128 + ty * 8 + 4];
            float4 b0 = *(const float4*)&Bt[d * 128 + tx * 8];
            float4 b1 = *(const float4*)&Bt[d * 128 + tx * 8 + 4];
            float a[8] = {a0.x, a0.y, a0.z, a0.w, a1.x, a1.y, a1.z, a1.w};
            float b[8] = {b0.x, b0.y, b0.z, b0.w, b1.x, b1.y, b1.z, b1.w};
#pragma unroll
            for (int i = 0; i < 8; i++)
#pragma unroll
                for (int j = 0; j < 8; j++) acc[i][j] += a[i] * b[j];
        }
    }

    float* C = g_sim + ((size_t)h * 2048 + m0 + ty * 8) * 8192 + n0 + tx * 8;
#pragma unroll
    for (int i = 0; i < 8; i++) {
        *(float4*)&C[(size_t)i * 8192]     = make_float4(acc[i][0], acc[i][1], acc[i][2], acc[i][3]);
        *(float4*)&C[(size_t)i * 8192 + 4] = make_float4(acc[i][4], acc[i][5], acc[i][6], acc[i][7]);
    }
}

// ---------------- flash-style causal attention (R1 arithmetic; heavy-first) ------
__global__ __launch_bounds__(256) void attn_kernel()
{
    const int r = blockIdx.y;
    const int qt = gridDim.x - 1 - blockIdx.x;      // heavy tiles launch first
    __shared__ float Qs[32 * 65];
    __shared__ float Ks[32 * 65];
    __shared__ float Vs[32 * 66];
    const int tid = threadIdx.x, w = tid >> 5, l = tid & 31;
    const float* qb = g_q + (size_t)r * 65536;
    const float* kb = g_k + (size_t)r * 65536;
    const float* vb = g_v + (size_t)r * 65536;

#pragma unroll
    for (int t = 0; t < 8; t++) {
        int li = tid + 256 * t;
        int row = li >> 6, c = li & 63;
        Qs[row * 65 + c] = qb[(size_t)(qt * 32 + row) * 64 + c];
    }

    const int q0 = qt * 32 + w * 4;
    float mrun[4], lse[4], o0[4], o1[4];
#pragma unroll
    for (int qi = 0; qi < 4; qi++) { mrun[qi] = -INFINITY; lse[qi] = 0.f; o0[qi] = 0.f; o1[qi] = 0.f; }

    for (int kt = 0; kt <= qt; kt++) {
        __syncthreads();
#pragma unroll
        for (int t = 0; t < 8; t++) {
            int li = tid + 256 * t;
            int row = li >> 6, c = li & 63;
            Ks[row * 65 + c] = kb[(size_t)(kt * 32 + row) * 64 + c];
            Vs[row * 66 + c] = vb[(size_t)(kt * 32 + row) * 64 + c];
        }
        __syncthreads();

        float s[4] = {0.f, 0.f, 0.f, 0.f};
#pragma unroll 8
        for (int d = 0; d < 64; d++) {
            float kd = Ks[l * 65 + d];
            s[0] += Qs[(w * 4 + 0) * 65 + d] * kd;
            s[1] += Qs[(w * 4 + 1) * 65 + d] * kd;
            s[2] += Qs[(w * 4 + 2) * 65 + d] * kd;
            s[3] += Qs[(w * 4 + 3) * 65 + d] * kd;
        }
        const int kk = kt * 32 + l;
#pragma unroll
        for (int qi = 0; qi < 4; qi++) {
            float sv = s[qi] * 0.125f;
            if (kk > q0 + qi) sv = -INFINITY;
            float mx = sv;
#pragma unroll
            for (int off = 16; off; off >>= 1) mx = fmaxf(mx, __shfl_xor_sync(FULLMASK, mx, off));
            float mnew = fmaxf(mrun[qi], mx);
            float p = __expf(sv - mnew);
            float corr = __expf(mrun[qi] - mnew);
            mrun[qi] = mnew;
            float ps = p;
#pragma unroll
            for (int off = 16; off; off >>= 1) ps += __shfl_xor_sync(FULLMASK, ps, off);
            lse[qi] = lse[qi] * corr + ps;
            o0[qi] *= corr; o1[qi] *= corr;
            s[qi] = p;
        }
#pragma unroll 4
        for (int j = 0; j < 32; j++) {
            float2 vv = *(const float2*)&Vs[j * 66 + 2 * l];
#pragma unroll
            for (int qi = 0; qi < 4; qi++) {
                float pj = __shfl_sync(FULLMASK, s[qi], j);
                o0[qi] += pj * vv.x;
                o1[qi] += pj * vv.y;
            }
        }
    }
#pragma unroll
    for (int qi = 0; qi < 4; qi++) {
        float inv = 1.f / lse[qi];
        float2 outv = make_float2(o0[qi] * inv, o1[qi] * inv);
        *(float2*)&g_attn[(size_t)r * 65536 + (size_t)(q0 + qi) * 64 + 2 * l] = outv;
    }
}

// ---------------- normalization kernels (R1-verbatim) ----------------------------
__global__ __launch_bounds__(256) void normk_kernel(const float* __restrict__ km)
{
    int w = threadIdx.x >> 5, l = threadIdx.x & 31;
    int row = blockIdx.x * 8 + w;                   // 0..65535 = h*8192+m
    float2 v = *(const float2*)(km + (size_t)row * 64 + 2 * l);
    float ss = v.x * v.x + v.y * v.y;
#pragma unroll
    for (int off = 16; off; off >>= 1) ss += __shfl_xor_sync(FULLMASK, ss, off);
    float sc = 1.f / (sqrtf(ss) + 1e-8f);
    float2 o = make_float2(v.x * sc, v.y * sc);
    *(float2*)&g_kn[(size_t)row * 64 + 2 * l] = o;
}

// q_mem[h][q] gathers q row 4*(h%4)+2*(q/1024)+(h/4); scale folds 1/sqrt(dk)
__global__ __launch_bounds__(256) void normq_kernel()
{
    int w = threadIdx.x >> 5, l = threadIdx.x & 31;
    int wq = blockIdx.x * 8 + w;                    // 0..16383
    int hm = wq >> 11, qi = wq & 2047;
    int src = 4 * (hm & 3) + 2 * (qi >> 10) + (hm >> 2);
    int s = qi & 1023;
    float2 v = *(const float2*)(g_q + ((size_t)src * 1024 + s) * 64 + 2 * l);
    float ss = v.x * v.x + v.y * v.y;
#pragma unroll
    for (int off = 16; off; off >>= 1) ss += __shfl_xor_sync(FULLMASK, ss, off);
    float sc = 0.125f / (sqrtf(ss) + 1e-8f);
    float2 o = make_float2(v.x * sc, v.y * sc);
    *(float2*)&g_qn[((size_t)hm * 2048 + qi) * 64 + 2 * l] = o;
}

// ---------------- exact top-32 + weighted gather (batched loads, same order) -----
__device__ __forceinline__ unsigned fkey(float f)
{
    unsigned b = __float_as_uint(f);
    return (b & 0x80000000u) ? ~b : (b | 0x80000000u);
}

__global__ __launch_bounds__(256) void topk_kernel(const float* __restrict__ vmem)
{
    int w = threadIdx.x >> 5, l = threadIdx.x & 31;
    int h = blockIdx.y;
    int q = blockIdx.x * 8 + w;                     // 0..2047
    const float* base = g_sim + ((size_t)h * 2048 + q) * 8192;

    unsigned held_u = 0u; int held_i = 0; float held_f = 0.f;
    unsigned minu = 0u;

    for (int cb = 0; cb < 16; cb++) {
        float4 vv[4];
#pragma unroll
        for (int u = 0; u < 4; u++)                 // batched: 4 independent loads
            vv[u] = *(const float4*)(base + (cb * 4 + u) * 128 + l * 4);
#pragma unroll
        for (int u = 0; u < 4; u++) {
            const int c = cb * 4 + u;
            float fv[4] = {vv[u].x, vv[u].y, vv[u].z, vv[u].w};
#pragma unroll
            for (int comp = 0; comp < 4; comp++) {
                float f = fv[comp];
                unsigned uu = fkey(f);
                unsigned mask = __ballot_sync(FULLMASK, uu > minu);
                while (mask) {
                    int b = __ffs(mask) - 1; mask &= mask - 1;
                    unsigned cu = __shfl_sync(FULLMASK, uu, b);
                    float cf = __shfl_sync(FULLMASK, f, b);
                    if (cu > minu) {
                        int ci = c * 128 + b * 4 + comp;
                        int ml = __ffs(__ballot_sync(FULLMASK, held_u == minu)) - 1;
                        if (l == ml) { held_u = cu; held_f = cf; held_i = ci; }
                        minu = __reduce_min_sync(FULLMASK, held_u);
                    }
                }
            }
        }
    }
    // weighted sum over the 32 selected memories
    float a0 = 0.f, a1 = 0.f;
    const float* vh = vmem + (size_t)h * 8192 * 64;
#pragma unroll 4
    for (int j = 0; j < 32; j++) {
        float sv = __shfl_sync(FULLMASK, held_f, j);
        int   si = __shfl_sync(FULLMASK, held_i, j);
        float2 vv2 = *(const float2*)(vh + (size_t)si * 64 + 2 * l);
        a0 += sv * vv2.x;
        a1 += sv * vv2.y;
    }
    float2 o = make_float2(a0, a1);
    *(float2*)&g_wsum[((size_t)h * 2048 + q) * 64 + 2 * l] = o;
}

// ---------------- gated combine into pre-Wo layout [b,s,H*dk] (R1-verbatim) ------
__global__ __launch_bounds__(256) void combine_kernel(const float* __restrict__ gate)
{
    int idx = blockIdx.x * 256 + threadIdx.x;       // 0 .. 2*1024*512-1
    int d = idx & 63, h = (idx >> 6) & 7, s = (idx >> 9) & 1023, b = idx >> 19;
    float g = 1.f / (1.f + __expf(-gate[h]));
    float wv = g_wsum[(((size_t)h * 2048) + (b << 10) + s) * 64 + d];
    float av = g_attn[((size_t)(2 * h + b) << 16) + (s << 6) + d];
    g_pre[idx] = g * wv + (1.f - g) * av;
}

// ---------------- host ----------------
extern "C" void kernel_launch(void* const* d_in, const int* in_sizes, int n_in,
                              void* d_out, int out_size)
{
    const float* x    = (const float*)d_in[0];
    const float* Wq   = (const float*)d_in[1];
    const float* bq   = (const float*)d_in[2];
    const float* Wk   = (const float*)d_in[3];
    const float* bk   = (const float*)d_in[4];
    const float* Wv   = (const float*)d_in[5];
    const float* bv   = (const float*)d_in[6];
    const float* Wo   = (const float*)d_in[7];
    const float* bo   = (const float*)d_in[8];
    const float* km   = (const float*)d_in[9];
    const float* vm   = (const float*)d_in[10];
    const float* gate = (const float*)d_in[11];
    float* out = (float*)d_out;
    (void)in_sizes; (void)n_in; (void)out_size;

    // QKV projections (fused 3-way launch; body/arithmetic identical to R1)
    gemmqkv_kernel<<<dim3(4, 16, 3), 256>>>(x, Wq, bq, Wk, bk, Wv, bv);

    // causal attention (heavy-first block order)
    attn_kernel<<<dim3(32, 16), 256>>>();

    // normalizations
    normq_kernel<<<2048, 256>>>();
    normk_kernel<<<8192, 256>>>(km);

    // sims SGEMM (bit-exact chain, all heads) + exact top-32 + gather
    simsgemm_kernel<<<dim3(64, 16, 8), 256>>>();
    topk_kernel<<<dim3(256, 8), 256>>>(vm);

    // gated combine + output projection (64x64 tiles, chain-identical)
    combine_kernel<<<4096, 256>>>(gate);
    gemmout64_kernel<<<dim3(8, 32), 256>>>(Wo, bo, out);
}

// round 17
// speedup vs baseline: 1.5636x; 1.5636x over previous
#include <cuda_runtime.h>
#include <math.h>

#define FULLMASK 0xffffffffu

// ---------------- scratch (__device__ globals; no allocs allowed) ----------------
__device__ float g_q[16 * 1024 * 64];    // [b*H][s][dk]
__device__ float g_k[16 * 1024 * 64];
__device__ float g_v[16 * 1024 * 64];
__device__ float g_attn[16 * 1024 * 64]; // attention output, same row layout
__device__ float g_qn[8 * 2048 * 64];    // normalized+scaled q_mem  [h][q][dk]
__device__ float g_kn[8 * 8192 * 64];    // normalized key memories  [h][m][dk]
__device__ float g_sim[8 * 2048 * 8192]; // fp32 sims, all heads (512 MB)
__device__ float g_wsum[8 * 2048 * 64];  // memory-path weighted sums [h][q][dk]

// ---------------- generic 128x128 tile SGEMM body (R1-verbatim arithmetic) -------
template <bool BT, bool HEADS>
__device__ __forceinline__ void gemm128_body(
    const float* __restrict__ A, int lda,
    const float* __restrict__ B, int ldb,
    const float* __restrict__ bias,
    float* __restrict__ C, int N, int K)
{
    __shared__ float As[128 * 33];
    __shared__ float Bs[4224];   // NT: [128][33] ; NN: [32][132]
    const int tid = threadIdx.x;
    const int tx = tid & 15, ty = tid >> 4;
    const int n0 = blockIdx.x * 128, m0 = blockIdx.y * 128;

    float acc[8][8];
#pragma unroll
    for (int i = 0; i < 8; i++)
#pragma unroll
        for (int j = 0; j < 8; j++) acc[i][j] = 0.f;

    for (int kt = 0; kt < K; kt += 32) {
#pragma unroll
        for (int t = 0; t < 4; t++) {               // A tile: 128 rows x 32 cols
            int li = tid + 256 * t;
            int row = li >> 3, c4 = li & 7;
            float4 va = *(const float4*)(A + (size_t)(m0 + row) * lda + kt + c4 * 4);
            float* dst = &As[row * 33 + c4 * 4];
            dst[0] = va.x; dst[1] = va.y; dst[2] = va.z; dst[3] = va.w;
        }
        if (BT) {
#pragma unroll
            for (int t = 0; t < 4; t++) {           // B tile: 128 rows x 32 cols
                int li = tid + 256 * t;
                int row = li >> 3, c4 = li & 7;
                float4 vb = *(const float4*)(B + (size_t)(n0 + row) * ldb + kt + c4 * 4);
                float* dst = &Bs[row * 33 + c4 * 4];
                dst[0] = vb.x; dst[1] = vb.y; dst[2] = vb.z; dst[3] = vb.w;
            }
        } else {
#pragma unroll
            for (int t = 0; t < 4; t++) {           // B tile: 32 rows x 128 cols
                int li = tid + 256 * t;
                int row = li >> 5, c4 = li & 31;
                float4 vb = *(const float4*)(B + (size_t)(kt + row) * ldb + n0 + c4 * 4);
                float* dst = &Bs[row * 132 + c4 * 4];
                dst[0] = vb.x; dst[1] = vb.y; dst[2] = vb.z; dst[3] = vb.w;
            }
        }
        __syncthreads();
#pragma unroll 4
        for (int d = 0; d < 32; d++) {
            float a[8], b[8];
#pragma unroll
            for (int i = 0; i < 8; i++) a[i] = As[(ty + 16 * i) * 33 + d];
#pragma unroll
            for (int j = 0; j < 8; j++)
                b[j] = BT ? Bs[(tx + 16 * j) * 33 + d] : Bs[d * 132 + tx + 16 * j];
#pragma unroll
            for (int i = 0; i < 8; i++)
#pragma unroll
                for (int j = 0; j < 8; j++) acc[i][j] += a[i] * b[j];
        }
        __syncthreads();
    }

#pragma unroll
    for (int i = 0; i < 8; i++) {
        int m = m0 + ty + 16 * i;
#pragma unroll
        for (int j = 0; j < 8; j++) {
            int n = n0 + tx + 16 * j;
            float val = acc[i][j] + (bias ? bias[n] : 0.f);
            if (HEADS) {
                int bb = m >> 10, ss = m & 1023, hh = n >> 6, dd = n & 63;
                C[(size_t)(((bb << 3) + hh) << 16) + (ss << 6) + dd] = val;
            } else {
                C[(size_t)m * N + n] = val;
            }
        }
    }
}

// fused QKV: blockIdx.z selects projection; body identical -> identical arithmetic
__global__ __launch_bounds__(256) void gemmqkv_kernel(
    const float* __restrict__ x,
    const float* __restrict__ Wq, const float* __restrict__ bq,
    const float* __restrict__ Wk, const float* __restrict__ bk,
    const float* __restrict__ Wv, const float* __restrict__ bv)
{
    const int z = blockIdx.z;
    const float* W = (z == 0) ? Wq : (z == 1) ? Wk : Wv;
    const float* b = (z == 0) ? bq : (z == 1) ? bk : bv;
    float* C = (z == 0) ? g_q : (z == 1) ? g_k : g_v;
    gemm128_body<false, true>(x, 512, W, 512, b, C, 512, 512);
}

// ---------------- out projection with fused gated combine ------------------------
// Identical GEMM structure/arithmetic to gemm128_body<false,false> (128x128 tile,
// kt += 32, d 0..31 ascending). The A element for (m, cc) is computed on the fly:
//   g*wv + (1-g)*av  — the exact expression combine_kernel used -> same bits.
__global__ __launch_bounds__(256) void gemmout_fused_kernel(
    const float* __restrict__ Wo, const float* __restrict__ bo,
    const float* __restrict__ gate, float* __restrict__ out)
{
    __shared__ float As[128 * 33];
    __shared__ float Bs[32 * 132];
    const int tid = threadIdx.x;
    const int tx = tid & 15, ty = tid >> 4;
    const int n0 = blockIdx.x * 128, m0 = blockIdx.y * 128;

    float acc[8][8];
#pragma unroll
    for (int i = 0; i < 8; i++)
#pragma unroll
        for (int j = 0; j < 8; j++) acc[i][j] = 0.f;

    for (int kt = 0; kt < 512; kt += 32) {
#pragma unroll
        for (int t = 0; t < 4; t++) {               // A tile: combine on the fly
            int li = tid + 256 * t;
            int row = li >> 3, c4 = li & 7;
            int m = m0 + row;                       // 0..2047
            int cc = kt + c4 * 4;                   // col, 4-aligned
            int h = cc >> 6, d0 = cc & 63;
            int bb = m >> 10, ss = m & 1023;
            float g = 1.f / (1.f + __expf(-gate[h]));
            float4 wv = *(const float4*)&g_wsum[(((size_t)h * 2048) + (bb << 10) + ss) * 64 + d0];
            float4 av = *(const float4*)&g_attn[((size_t)(2 * h + bb) << 16) + (ss << 6) + d0];
            float* dst = &As[row * 33 + c4 * 4];
            dst[0] = g * wv.x + (1.f - g) * av.x;
            dst[1] = g * wv.y + (1.f - g) * av.y;
            dst[2] = g * wv.z + (1.f - g) * av.z;
            dst[3] = g * wv.w + (1.f - g) * av.w;
        }
#pragma unroll
        for (int t = 0; t < 4; t++) {               // B tile: 32 rows x 128 cols
            int li = tid + 256 * t;
            int row = li >> 5, c4 = li & 31;
            float4 vb = *(const float4*)(Wo + (size_t)(kt + row) * 512 + n0 + c4 * 4);
            float* dst = &Bs[row * 132 + c4 * 4];
            dst[0] = vb.x; dst[1] = vb.y; dst[2] = vb.z; dst[3] = vb.w;
        }
        __syncthreads();
#pragma unroll 4
        for (int d = 0; d < 32; d++) {
            float a[8], b[8];
#pragma unroll
            for (int i = 0; i < 8; i++) a[i] = As[(ty + 16 * i) * 33 + d];
#pragma unroll
            for (int j = 0; j < 8; j++) b[j] = Bs[d * 132 + tx + 16 * j];
#pragma unroll
            for (int i = 0; i < 8; i++)
#pragma unroll
                for (int j = 0; j < 8; j++) acc[i][j] += a[i] * b[j];
        }
        __syncthreads();
    }

#pragma unroll
    for (int i = 0; i < 8; i++) {
        int m = m0 + ty + 16 * i;
#pragma unroll
        for (int j = 0; j < 8; j++) {
            int n = n0 + tx + 16 * j;
            out[(size_t)m * 512 + n] = acc[i][j] + bo[n];
        }
    }
}

// ---------------- fast sims SGEMM (R10-verbatim: transposed smem + lds.128) ------
__global__ __launch_bounds__(256) void simsgemm_kernel()
{
    __shared__ float At[32 * 128];
    __shared__ float Bt[32 * 128];
    const int h = blockIdx.z;
    const int n0 = blockIdx.x * 128, m0 = blockIdx.y * 128;
    const int tid = threadIdx.x;
    const int tx = tid & 15, ty = tid >> 4;
    const float* A = g_qn + (size_t)h * 2048 * 64 + (size_t)m0 * 64;
    const float* B = g_kn + (size_t)h * 8192 * 64 + (size_t)n0 * 64;

    float acc[8][8];
#pragma unroll
    for (int i = 0; i < 8; i++)
#pragma unroll
        for (int j = 0; j < 8; j++) acc[i][j] = 0.f;

    for (int kc = 0; kc < 64; kc += 32) {
        if (kc) __syncthreads();
#pragma unroll
        for (int t = 0; t < 4; t++) {               // 1024 float4 per tile, transposed store
            int li = tid + 256 * t;                 // 0..1023
            int c4 = li >> 7;                       // 0..7 (float4 column within chunk)
            int row = li & 127;                     // tile row
            float4 va = *(const float4*)(A + (size_t)row * 64 + kc + c4 * 4);
            At[(c4 * 4 + 0) * 128 + row] = va.x;
            At[(c4 * 4 + 1) * 128 + row] = va.y;
            At[(c4 * 4 + 2) * 128 + row] = va.z;
            At[(c4 * 4 + 3) * 128 + row] = va.w;
            float4 vb = *(const float4*)(B + (size_t)row * 64 + kc + c4 * 4);
            Bt[(c4 * 4 + 0) * 128 + row] = vb.x;
            Bt[(c4 * 4 + 1) * 128 + row] = vb.y;
            Bt[(c4 * 4 + 2) * 128 + row] = vb.z;
            Bt[(c4 * 4 + 3) * 128 + row] = vb.w;
        }
        __syncthreads();

#pragma unroll 8
        for (int d = 0; d < 32; d++) {
            float4 a0 = *(const float4*)&At[d * 128 + ty * 8];
            float4 a1 = *(const float4*)&At[d * 128 + ty * 8 + 4];
            float4 b0 = *(const float4*)&Bt[d * 128 + tx * 8];
            float4 b1 = *(const float4*)&Bt[d * 128 + tx * 8 + 4];
            float a[8] = {a0.x, a0.y, a0.z, a0.w, a1.x, a1.y, a1.z, a1.w};
            float b[8] = {b0.x, b0.y, b0.z, b0.w, b1.x, b1.y, b1.z, b1.w};
#pragma unroll
            for (int i = 0; i < 8; i++)
#pragma unroll
                for (int j = 0; j < 8; j++) acc[i][j] += a[i] * b[j];
        }
    }

    float* C = g_sim + ((size_t)h * 2048 + m0 + ty * 8) * 8192 + n0 + tx * 8;
#pragma unroll
    for (int i = 0; i < 8; i++) {
        *(float4*)&C[(size_t)i * 8192]     = make_float4(acc[i][0], acc[i][1], acc[i][2], acc[i][3]);
        *(float4*)&C[(size_t)i * 8192 + 4] = make_float4(acc[i][4], acc[i][5], acc[i][6], acc[i][7]);
    }
}

// ---------------- flash-style causal attention (R1-verbatim) ---------------------
__global__ __launch_bounds__(256) void attn_kernel()
{
    const int r = blockIdx.y, qt = blockIdx.x;
    __shared__ float Qs[32 * 65];
    __shared__ float Ks[32 * 65];
    __shared__ float Vs[32 * 66];
    const int tid = threadIdx.x, w = tid >> 5, l = tid & 31;
    const float* qb = g_q + (size_t)r * 65536;
    const float* kb = g_k + (size_t)r * 65536;
    const float* vb = g_v + (size_t)r * 65536;

#pragma unroll
    for (int t = 0; t < 8; t++) {
        int li = tid + 256 * t;
        int row = li >> 6, c = li & 63;
        Qs[row * 65 + c] = qb[(size_t)(qt * 32 + row) * 64 + c];
    }

    const int q0 = qt * 32 + w * 4;
    float mrun[4], lse[4], o0[4], o1[4];
#pragma unroll
    for (int qi = 0; qi < 4; qi++) { mrun[qi] = -INFINITY; lse[qi] = 0.f; o0[qi] = 0.f; o1[qi] = 0.f; }

    for (int kt = 0; kt <= qt; kt++) {
        __syncthreads();
#pragma unroll
        for (int t = 0; t < 8; t++) {
            int li = tid + 256 * t;
            int row = li >> 6, c = li & 63;
            Ks[row * 65 + c] = kb[(size_t)(kt * 32 + row) * 64 + c];
            Vs[row * 66 + c] = vb[(size_t)(kt * 32 + row) * 64 + c];
        }
        __syncthreads();

        float s[4] = {0.f, 0.f, 0.f, 0.f};
#pragma unroll 8
        for (int d = 0; d < 64; d++) {
            float kd = Ks[l * 65 + d];
            s[0] += Qs[(w * 4 + 0) * 65 + d] * kd;
            s[1] += Qs[(w * 4 + 1) * 65 + d] * kd;
            s[2] += Qs[(w * 4 + 2) * 65 + d] * kd;
            s[3] += Qs[(w * 4 + 3) * 65 + d] * kd;
        }
        const int kk = kt * 32 + l;
#pragma unroll
        for (int qi = 0; qi < 4; qi++) {
            float sv = s[qi] * 0.125f;
            if (kk > q0 + qi) sv = -INFINITY;
            float mx = sv;
#pragma unroll
            for (int off = 16; off; off >>= 1) mx = fmaxf(mx, __shfl_xor_sync(FULLMASK, mx, off));
            float mnew = fmaxf(mrun[qi], mx);
            float p = __expf(sv - mnew);
            float corr = __expf(mrun[qi] - mnew);
            mrun[qi] = mnew;
            float ps = p;
#pragma unroll
            for (int off = 16; off; off >>= 1) ps += __shfl_xor_sync(FULLMASK, ps, off);
            lse[qi] = lse[qi] * corr + ps;
            o0[qi] *= corr; o1[qi] *= corr;
            s[qi] = p;
        }
#pragma unroll 4
        for (int j = 0; j < 32; j++) {
            float2 vv = *(const float2*)&Vs[j * 66 + 2 * l];
#pragma unroll
            for (int qi = 0; qi < 4; qi++) {
                float pj = __shfl_sync(FULLMASK, s[qi], j);
                o0[qi] += pj * vv.x;
                o1[qi] += pj * vv.y;
            }
        }
    }
#pragma unroll
    for (int qi = 0; qi < 4; qi++) {
        float inv = 1.f / lse[qi];
        float2 outv = make_float2(o0[qi] * inv, o1[qi] * inv);
        *(float2*)&g_attn[(size_t)r * 65536 + (size_t)(q0 + qi) * 64 + 2 * l] = outv;
    }
}

// ---------------- normalization kernels (R1-verbatim) ----------------------------
__global__ __launch_bounds__(256) void normk_kernel(const float* __restrict__ km)
{
    int w = threadIdx.x >> 5, l = threadIdx.x & 31;
    int row = blockIdx.x * 8 + w;                   // 0..65535 = h*8192+m
    float2 v = *(const float2*)(km + (size_t)row * 64 + 2 * l);
    float ss = v.x * v.x + v.y * v.y;
#pragma unroll
    for (int off = 16; off; off >>= 1) ss += __shfl_xor_sync(FULLMASK, ss, off);
    float sc = 1.f / (sqrtf(ss) + 1e-8f);
    float2 o = make_float2(v.x * sc, v.y * sc);
    *(float2*)&g_kn[(size_t)row * 64 + 2 * l] = o;
}

// q_mem[h][q] gathers q row 4*(h%4)+2*(q/1024)+(h/4); scale folds 1/sqrt(dk)
__global__ __launch_bounds__(256) void normq_kernel()
{
    int w = threadIdx.x >> 5, l = threadIdx.x & 31;
    int wq = blockIdx.x * 8 + w;                    // 0..16383
    int hm = wq >> 11, qi = wq & 2047;
    int src = 4 * (hm & 3) + 2 * (qi >> 10) + (hm >> 2);
    int s = qi & 1023;
    float2 v = *(const float2*)(g_q + ((size_t)src * 1024 + s) * 64 + 2 * l);
    float ss = v.x * v.x + v.y * v.y;
#pragma unroll
    for (int off = 16; off; off >>= 1) ss += __shfl_xor_sync(FULLMASK, ss, off);
    float sc = 0.125f / (sqrtf(ss) + 1e-8f);
    float2 o = make_float2(v.x * sc, v.y * sc);
    *(float2*)&g_qn[((size_t)hm * 2048 + qi) * 64 + 2 * l] = o;
}

// ---------------- exact top-32 + weighted gather (batched loads, same order) -----
__device__ __forceinline__ unsigned fkey(float f)
{
    unsigned b = __float_as_uint(f);
    return (b & 0x80000000u) ? ~b : (b | 0x80000000u);
}

__global__ __launch_bounds__(256) void topk_kernel(const float* __restrict__ vmem)
{
    int w = threadIdx.x >> 5, l = threadIdx.x & 31;
    int h = blockIdx.y;
    int q = blockIdx.x * 8 + w;                     // 0..2047
    const float* base = g_sim + ((size_t)h * 2048 + q) * 8192;

    unsigned held_u = 0u; int held_i = 0; float held_f = 0.f;
    unsigned minu = 0u;

    for (int cb = 0; cb < 16; cb++) {
        float4 vv[4];
#pragma unroll
        for (int u = 0; u < 4; u++)                 // batched: 4 independent loads
            vv[u] = *(const float4*)(base + (cb * 4 + u) * 128 + l * 4);
#pragma unroll
        for (int u = 0; u < 4; u++) {
            const int c = cb * 4 + u;
            float fv[4] = {vv[u].x, vv[u].y, vv[u].z, vv[u].w};
#pragma unroll
            for (int comp = 0; comp < 4; comp++) {
                float f = fv[comp];
                unsigned uu = fkey(f);
                unsigned mask = __ballot_sync(FULLMASK, uu > minu);
                while (mask) {
                    int b = __ffs(mask) - 1; mask &= mask - 1;
                    unsigned cu = __shfl_sync(FULLMASK, uu, b);
                    float cf = __shfl_sync(FULLMASK, f, b);
                    if (cu > minu) {
                        int ci = c * 128 + b * 4 + comp;
                        int ml = __ffs(__ballot_sync(FULLMASK, held_u == minu)) - 1;
                        if (l == ml) { held_u = cu; held_f = cf; held_i = ci; }
                        minu = __reduce_min_sync(FULLMASK, held_u);
                    }
                }
            }
        }
    }
    // weighted sum over the 32 selected memories
    float a0 = 0.f, a1 = 0.f;
    const float* vh = vmem + (size_t)h * 8192 * 64;
#pragma unroll 4
    for (int j = 0; j < 32; j++) {
        float sv = __shfl_sync(FULLMASK, held_f, j);
        int   si = __shfl_sync(FULLMASK, held_i, j);
        float2 vv2 = *(const float2*)(vh + (size_t)si * 64 + 2 * l);
        a0 += sv * vv2.x;
        a1 += sv * vv2.y;
    }
    float2 o = make_float2(a0, a1);
    *(float2*)&g_wsum[((size_t)h * 2048 + q) * 64 + 2 * l] = o;
}

// ---------------- host ----------------
extern "C" void kernel_launch(void* const* d_in, const int* in_sizes, int n_in,
                              void* d_out, int out_size)
{
    const float* x    = (const float*)d_in[0];
    const float* Wq   = (const float*)d_in[1];
    const float* bq   = (const float*)d_in[2];
    const float* Wk   = (const float*)d_in[3];
    const float* bk   = (const float*)d_in[4];
    const float* Wv   = (const float*)d_in[5];
    const float* bv   = (const float*)d_in[6];
    const float* Wo   = (const float*)d_in[7];
    const float* bo   = (const float*)d_in[8];
    const float* km   = (const float*)d_in[9];
    const float* vm   = (const float*)d_in[10];
    const float* gate = (const float*)d_in[11];
    float* out = (float*)d_out;
    (void)in_sizes; (void)n_in; (void)out_size;

    // QKV projections (fused 3-way launch; body/arithmetic identical to R1)
    gemmqkv_kernel<<<dim3(4, 16, 3), 256>>>(x, Wq, bq, Wk, bk, Wv, bv);

    // causal attention (R1 block order)
    attn_kernel<<<dim3(32, 16), 256>>>();

    // normalizations
    normq_kernel<<<2048, 256>>>();
    normk_kernel<<<8192, 256>>>(km);

    // sims SGEMM (bit-exact chain, all heads) + exact top-32 + gather
    simsgemm_kernel<<<dim3(64, 16, 8), 256>>>();
    topk_kernel<<<dim3(256, 8), 256>>>(vm);

    // output projection with fused gated combine (bit-identical A elements)
    gemmout_fused_kernel<<<dim3(4, 16), 256>>>(Wo, bo, gate, out);
}